// round 2
// baseline (speedup 1.0000x reference)
#include <cuda_runtime.h>

#define DIM   512
#define N_CB  8192
#define M_Z   32768
#define QN    16777216   // M_Z * DIM

// ---- scratch (device globals; no allocation) ----
__device__ float g_qcb[(size_t)N_CB * DIM];   // 16 MB  quant_codebook (fp32)
__device__ float g_cn [(size_t)N_CB * DIM];   // 16 MB  normalized codebook
__device__ float g_zp [(size_t)M_Z * DIM];    // 64 MB  z_proj
__device__ int   g_idx[M_Z];
__device__ float g_partial[M_Z];

// ============================================================
// C = A @ W^T + bias   (A: MxK row-major, W: NxK row-major)
// 128x128 CTA tile, K-chunks of 16, 8x8 per thread, 256 threads
// which_out: 0 -> g_qcb, 1 -> g_zp
// ============================================================
__global__ __launch_bounds__(256, 2)
void gemm_bias_nt(const float* __restrict__ A, const float* __restrict__ W,
                  const float* __restrict__ bias, int M, int N, int K, int which_out)
{
    float* __restrict__ C = which_out ? g_zp : g_qcb;
    __shared__ float As[16][128];
    __shared__ float Ws[16][128];
    const int tid = threadIdx.x;
    const int tx  = tid & 15;
    const int ty  = tid >> 4;
    const int row0 = blockIdx.y * 128;
    const int col0 = blockIdx.x * 128;

    float acc[8][8];
    #pragma unroll
    for (int i = 0; i < 8; i++)
        #pragma unroll
        for (int j = 0; j < 8; j++) acc[i][j] = 0.0f;

    for (int k0 = 0; k0 < K; k0 += 16) {
        #pragma unroll
        for (int v = tid; v < 512; v += 256) {
            int r  = v >> 2;
            int kc = (v & 3) << 2;
            float4 a = *(const float4*)(A + (size_t)(row0 + r) * K + k0 + kc);
            As[kc + 0][r] = a.x; As[kc + 1][r] = a.y;
            As[kc + 2][r] = a.z; As[kc + 3][r] = a.w;
            float4 w = *(const float4*)(W + (size_t)(col0 + r) * K + k0 + kc);
            Ws[kc + 0][r] = w.x; Ws[kc + 1][r] = w.y;
            Ws[kc + 2][r] = w.z; Ws[kc + 3][r] = w.w;
        }
        __syncthreads();
        #pragma unroll
        for (int kk = 0; kk < 16; kk++) {
            float a[8], b[8];
            *(float4*)(a)     = *(const float4*)&As[kk][ty * 8];
            *(float4*)(a + 4) = *(const float4*)&As[kk][ty * 8 + 4];
            *(float4*)(b)     = *(const float4*)&Ws[kk][tx * 8];
            *(float4*)(b + 4) = *(const float4*)&Ws[kk][tx * 8 + 4];
            #pragma unroll
            for (int i = 0; i < 8; i++)
                #pragma unroll
                for (int j = 0; j < 8; j++)
                    acc[i][j] = fmaf(a[i], b[j], acc[i][j]);
        }
        __syncthreads();
    }

    float bs[8];
    #pragma unroll
    for (int j = 0; j < 8; j++) bs[j] = bias[col0 + tx * 8 + j];

    #pragma unroll
    for (int i = 0; i < 8; i++) {
        size_t row = (size_t)(row0 + ty * 8 + i);
        float* cp = C + row * N + col0 + tx * 8;
        float4 o0, o1;
        o0.x = acc[i][0] + bs[0]; o0.y = acc[i][1] + bs[1];
        o0.z = acc[i][2] + bs[2]; o0.w = acc[i][3] + bs[3];
        o1.x = acc[i][4] + bs[4]; o1.y = acc[i][5] + bs[5];
        o1.z = acc[i][6] + bs[6]; o1.w = acc[i][7] + bs[7];
        *(float4*)(cp)     = o0;
        *(float4*)(cp + 4) = o1;
    }
}

// ============================================================
// row-normalize g_qcb -> g_cn  (x / max(||x||, 1e-12))
// one warp per row
// ============================================================
__global__ void normalize_rows()
{
    int row  = blockIdx.x * 8 + (threadIdx.x >> 5);
    int lane = threadIdx.x & 31;
    const float* x = g_qcb + (size_t)row * DIM;
    float4 v[4];
    float s = 0.0f;
    #pragma unroll
    for (int it = 0; it < 4; it++) {
        v[it] = *(const float4*)(x + lane * 4 + it * 128);
        s += v[it].x * v[it].x + v[it].y * v[it].y
           + v[it].z * v[it].z + v[it].w * v[it].w;
    }
    #pragma unroll
    for (int off = 16; off > 0; off >>= 1)
        s += __shfl_xor_sync(0xFFFFFFFFu, s, off);
    float scale = 1.0f / fmaxf(sqrtf(s), 1e-12f);
    float* y = g_cn + (size_t)row * DIM;
    #pragma unroll
    for (int it = 0; it < 4; it++) {
        float4 o;
        o.x = v[it].x * scale; o.y = v[it].y * scale;
        o.z = v[it].z * scale; o.w = v[it].w * scale;
        *(float4*)(y + lane * 4 + it * 128) = o;
    }
}

// ============================================================
// fused distances + argmax:  argmax_n ( z_proj[m] . cn[n] )
// CTA: 128 rows, loops all 8192 codes in 128-wide tiles.
// ============================================================
__global__ __launch_bounds__(256, 2)
void dist_argmax()
{
    __shared__ float As[16][128];
    __shared__ float Ws[16][128];
    __shared__ float red_v[16 * 128];
    __shared__ int   red_i[16 * 128];

    const int tid = threadIdx.x;
    const int tx  = tid & 15;
    const int ty  = tid >> 4;
    const int row0 = blockIdx.x * 128;

    float bestv[8];
    int   besti[8];
    #pragma unroll
    for (int i = 0; i < 8; i++) { bestv[i] = -3.4e38f; besti[i] = 0; }

    for (int n0 = 0; n0 < N_CB; n0 += 128) {
        float acc[8][8];
        #pragma unroll
        for (int i = 0; i < 8; i++)
            #pragma unroll
            for (int j = 0; j < 8; j++) acc[i][j] = 0.0f;

        for (int k0 = 0; k0 < DIM; k0 += 16) {
            #pragma unroll
            for (int v = tid; v < 512; v += 256) {
                int r  = v >> 2;
                int kc = (v & 3) << 2;
                float4 a = *(const float4*)(g_zp + (size_t)(row0 + r) * DIM + k0 + kc);
                As[kc + 0][r] = a.x; As[kc + 1][r] = a.y;
                As[kc + 2][r] = a.z; As[kc + 3][r] = a.w;
                float4 w = *(const float4*)(g_cn + (size_t)(n0 + r) * DIM + k0 + kc);
                Ws[kc + 0][r] = w.x; Ws[kc + 1][r] = w.y;
                Ws[kc + 2][r] = w.z; Ws[kc + 3][r] = w.w;
            }
            __syncthreads();
            #pragma unroll
            for (int kk = 0; kk < 16; kk++) {
                float a[8], b[8];
                *(float4*)(a)     = *(const float4*)&As[kk][ty * 8];
                *(float4*)(a + 4) = *(const float4*)&As[kk][ty * 8 + 4];
                *(float4*)(b)     = *(const float4*)&Ws[kk][tx * 8];
                *(float4*)(b + 4) = *(const float4*)&Ws[kk][tx * 8 + 4];
                #pragma unroll
                for (int i = 0; i < 8; i++)
                    #pragma unroll
                    for (int j = 0; j < 8; j++)
                        acc[i][j] = fmaf(a[i], b[j], acc[i][j]);
            }
            __syncthreads();
        }

        // per-thread running argmax; j ascending + strict '>' keeps first max
        #pragma unroll
        for (int i = 0; i < 8; i++) {
            #pragma unroll
            for (int j = 0; j < 8; j++) {
                float v = acc[i][j];
                if (v > bestv[i]) { bestv[i] = v; besti[i] = n0 + tx * 8 + j; }
            }
        }
    }

    #pragma unroll
    for (int i = 0; i < 8; i++) {
        red_v[tx * 128 + ty * 8 + i] = bestv[i];
        red_i[tx * 128 + ty * 8 + i] = besti[i];
    }
    __syncthreads();

    if (tid < 128) {
        float bv = red_v[tid];
        int   bi = red_i[tid];
        #pragma unroll
        for (int t = 1; t < 16; t++) {
            float v = red_v[t * 128 + tid];
            int   n = red_i[t * 128 + tid];
            if (v > bv || (v == bv && n < bi)) { bv = v; bi = n; }
        }
        g_idx[row0 + tid] = bi;
    }
}

// ============================================================
// gather quantized = z + (q - z), per-row partial of (q-z)^2,
// and idx (as float) into the output tail.
// ============================================================
__global__ void gather_loss(const float* __restrict__ z, float* __restrict__ out,
                            long long out_size)
{
    int row = blockIdx.x;
    int t   = threadIdx.x;   // 128 threads
    int id  = g_idx[row];
    const float* q  = g_qcb + (size_t)id * DIM;
    const float* zr = z + (size_t)row * DIM;
    float* oq = out + (size_t)row * DIM;

    float s = 0.0f;
    #pragma unroll
    for (int c = t * 4; c < DIM; c += 512) {
        float4 qv = *(const float4*)(q + c);
        float4 zv = *(const float4*)(zr + c);
        float4 o;
        float d;
        d = qv.x - zv.x; o.x = zv.x + d; s = fmaf(d, d, s);
        d = qv.y - zv.y; o.y = zv.y + d; s = fmaf(d, d, s);
        d = qv.z - zv.z; o.z = zv.z + d; s = fmaf(d, d, s);
        d = qv.w - zv.w; o.w = zv.w + d; s = fmaf(d, d, s);
        *(float4*)(oq + c) = o;
    }

    __shared__ float red[128];
    red[t] = s;
    __syncthreads();
    #pragma unroll
    for (int off = 64; off > 0; off >>= 1) {
        if (t < off) red[t] += red[t + off];
        __syncthreads();
    }
    if (t == 0) {
        g_partial[row] = red[0];
        long long pos = (long long)QN + 1 + row;
        if (pos < out_size) out[pos] = (float)id;
    }
}

__global__ void finalize_loss(float* __restrict__ out, long long out_size)
{
    __shared__ float red[256];
    int t = threadIdx.x;
    float s = 0.0f;
    for (int i = t; i < M_Z; i += 256) s += g_partial[i];  // fixed order: deterministic
    red[t] = s;
    __syncthreads();
    #pragma unroll
    for (int off = 128; off > 0; off >>= 1) {
        if (t < off) red[t] += red[t + off];
        __syncthreads();
    }
    if (t == 0 && (long long)QN < out_size)
        out[QN] = red[0] * (1.25f / 16777216.0f);   // (commit + 0.25*codebook) / (B*T*D)
}

__global__ void zero_range(float* __restrict__ out, long long begin, long long end)
{
    long long stride = (long long)gridDim.x * blockDim.x;
    for (long long i = begin + (long long)blockIdx.x * blockDim.x + threadIdx.x;
         i < end; i += stride)
        out[i] = 0.0f;
}

// ============================================================
extern "C" void kernel_launch(void* const* d_in, const int* in_sizes, int n_in,
                              void* d_out, int out_size)
{
    const float* z     = (const float*)d_in[0];   // [8,4096,512]
    const float* emb   = (const float*)d_in[1];   // [8192,512]
    const float* emb_w = (const float*)d_in[2];   // [512,512]
    const float* emb_b = (const float*)d_in[3];   // [512]
    const float* zw    = (const float*)d_in[4];   // [512,512]
    const float* zb    = (const float*)d_in[5];   // [512]
    // d_in[6] = l2_scale: positive per-row scaling, argmin-invariant -> unused
    float* out = (float*)d_out;
    long long osz = (long long)out_size;

    // K1: quant_codebook = emb @ emb_w^T + emb_b  -> g_qcb
    gemm_bias_nt<<<dim3(4, 64), 256>>>(emb, emb_w, emb_b, N_CB, DIM, DIM, 0);
    // K2: g_cn = normalize_rows(g_qcb)
    normalize_rows<<<N_CB / 8, 256>>>();
    // K3: z_proj = z @ zw^T + zb -> g_zp
    gemm_bias_nt<<<dim3(4, 256), 256>>>(z, zw, zb, M_Z, DIM, DIM, 1);
    // K4: fused distances + argmax -> g_idx
    dist_argmax<<<M_Z / 128, 256>>>();
    // K5: quantized out + per-row loss partials + idx tail
    gather_loss<<<M_Z, 128>>>(z, out, osz);
    // K6: vq_loss
    finalize_loss<<<1, 256>>>(out, osz);
    // tail insurance against poisoned bytes beyond the expected layout
    long long need = (long long)QN + 1 + M_Z;
    if (osz > need) zero_range<<<256, 256>>>(out, need, osz);
}

// round 6
// speedup vs baseline: 1.8051x; 1.8051x over previous
#include <cuda_runtime.h>
#include <cuda_bf16.h>
#include <cstdint>

#define DIM   512
#define N_CB  8192
#define M_Z   32768
#define QN    16777216   // M_Z * DIM
#define CAP   32
#define MARGIN 0.2f

// ---- scratch (device globals; no allocation) ----
__device__ float g_qcb[(size_t)N_CB * DIM];           // quant_codebook fp32 (16MB)
__device__ float g_u  [(size_t)N_CB * DIM];           // U = diag(1/||c||) (qcb @ W) fp32 (16MB)
__device__ __nv_bfloat16 g_ub[(size_t)N_CB * DIM];    // U bf16 (8MB)
__device__ __nv_bfloat16 g_zb[(size_t)M_Z * DIM];     // z bf16 (32MB)
__device__ float g_rs  [N_CB];                        // 1/||c||
__device__ float g_beta[N_CB];                        // (b . c)/||c||
__device__ unsigned g_cand[(size_t)M_Z * CAP];
__device__ int   g_ccnt[M_Z];
__device__ int   g_idx[M_Z];
__device__ float g_partial[M_Z];

// ============================================================
// base-ISA PTX helpers (no sm_103a-specific instructions)
// ============================================================
__device__ __forceinline__ uint32_t smem_u32(const void* p) {
    uint32_t a;
    asm("{ .reg .u64 t; cvta.to.shared.u64 t, %1; cvt.u32.u64 %0, t; }" : "=r"(a) : "l"(p));
    return a;
}
__device__ __forceinline__ void cp16(uint32_t dst, const void* src) {
    asm volatile("cp.async.cg.shared.global [%0], [%1], 16;" :: "r"(dst), "l"(src) : "memory");
}
#define CP_COMMIT() asm volatile("cp.async.commit_group;" ::: "memory")
#define CP_WAIT(N)  asm volatile("cp.async.wait_group %0;" :: "n"(N) : "memory")

__device__ __forceinline__ void ldmatrix_x4(uint32_t* r, uint32_t addr) {
    asm volatile("ldmatrix.sync.aligned.m8n8.x4.shared.b16 {%0,%1,%2,%3}, [%4];"
        : "=r"(r[0]), "=r"(r[1]), "=r"(r[2]), "=r"(r[3]) : "r"(addr));
}
__device__ __forceinline__ void mma_bf16(float* d, const uint32_t* a, uint32_t b0, uint32_t b1) {
    asm volatile("mma.sync.aligned.m16n8k16.row.col.f32.bf16.bf16.f32 "
        "{%0,%1,%2,%3}, {%4,%5,%6,%7}, {%8,%9}, {%0,%1,%2,%3};"
        : "+f"(d[0]), "+f"(d[1]), "+f"(d[2]), "+f"(d[3])
        : "r"(a[0]), "r"(a[1]), "r"(a[2]), "r"(a[3]), "r"(b0), "r"(b1));
}

// ============================================================
// K1: qcb = emb @ emb_w^T + emb_b   (NT, fp32)  128x128 tiles
// ============================================================
__global__ __launch_bounds__(256, 2)
void gemm_bias_nt(const float* __restrict__ A, const float* __restrict__ W,
                  const float* __restrict__ bias, int K)
{
    __shared__ float As[16][128];
    __shared__ float Ws[16][128];
    const int tid = threadIdx.x;
    const int tx  = tid & 15;
    const int ty  = tid >> 4;
    const int row0 = blockIdx.y * 128;
    const int col0 = blockIdx.x * 128;

    float acc[8][8];
    #pragma unroll
    for (int i = 0; i < 8; i++)
        #pragma unroll
        for (int j = 0; j < 8; j++) acc[i][j] = 0.0f;

    for (int k0 = 0; k0 < K; k0 += 16) {
        #pragma unroll
        for (int v = tid; v < 512; v += 256) {
            int r  = v >> 2;
            int kc = (v & 3) << 2;
            float4 a = *(const float4*)(A + (size_t)(row0 + r) * K + k0 + kc);
            As[kc + 0][r] = a.x; As[kc + 1][r] = a.y;
            As[kc + 2][r] = a.z; As[kc + 3][r] = a.w;
            float4 w = *(const float4*)(W + (size_t)(col0 + r) * K + k0 + kc);
            Ws[kc + 0][r] = w.x; Ws[kc + 1][r] = w.y;
            Ws[kc + 2][r] = w.z; Ws[kc + 3][r] = w.w;
        }
        __syncthreads();
        #pragma unroll
        for (int kk = 0; kk < 16; kk++) {
            float a[8], b[8];
            *(float4*)(a)     = *(const float4*)&As[kk][ty * 8];
            *(float4*)(a + 4) = *(const float4*)&As[kk][ty * 8 + 4];
            *(float4*)(b)     = *(const float4*)&Ws[kk][tx * 8];
            *(float4*)(b + 4) = *(const float4*)&Ws[kk][tx * 8 + 4];
            #pragma unroll
            for (int i = 0; i < 8; i++)
                #pragma unroll
                for (int j = 0; j < 8; j++)
                    acc[i][j] = fmaf(a[i], b[j], acc[i][j]);
        }
        __syncthreads();
    }

    float bs[8];
    #pragma unroll
    for (int j = 0; j < 8; j++) bs[j] = bias[col0 + tx * 8 + j];

    #pragma unroll
    for (int i = 0; i < 8; i++) {
        size_t row = (size_t)(row0 + ty * 8 + i);
        float* cp = g_qcb + row * DIM + col0 + tx * 8;
        *(float4*)(cp)     = make_float4(acc[i][0]+bs[0], acc[i][1]+bs[1], acc[i][2]+bs[2], acc[i][3]+bs[3]);
        *(float4*)(cp + 4) = make_float4(acc[i][4]+bs[4], acc[i][5]+bs[5], acc[i][6]+bs[6], acc[i][7]+bs[7]);
    }
}

// ============================================================
// K2: per-row 1/||c|| and beta = (z_proj_b . c)/||c||    (warp/row)
// ============================================================
__global__ void rownorm_beta(const float* __restrict__ zpb)
{
    int row  = blockIdx.x * 8 + (threadIdx.x >> 5);
    int lane = threadIdx.x & 31;
    const float* x = g_qcb + (size_t)row * DIM;
    float s2 = 0.0f, sb = 0.0f;
    #pragma unroll
    for (int it = 0; it < 4; it++) {
        float4 v = *(const float4*)(x + lane * 4 + it * 128);
        float4 b = *(const float4*)(zpb + lane * 4 + it * 128);
        s2 += v.x*v.x + v.y*v.y + v.z*v.z + v.w*v.w;
        sb += v.x*b.x + v.y*b.y + v.z*b.z + v.w*b.w;
    }
    #pragma unroll
    for (int off = 16; off > 0; off >>= 1) {
        s2 += __shfl_xor_sync(0xFFFFFFFFu, s2, off);
        sb += __shfl_xor_sync(0xFFFFFFFFu, sb, off);
    }
    float rs = 1.0f / fmaxf(sqrtf(s2), 1e-12f);
    if (lane == 0) { g_rs[row] = rs; g_beta[row] = sb * rs; }
}

// ============================================================
// K3: U = (g_qcb @ W) * rs[row]   (NN, fp32)  -> g_u fp32 + g_ub bf16
// NOTE: g_qcb/g_u referenced from DEVICE code (host cannot pass
// __device__ symbol addresses — that was the round-5 bug).
// ============================================================
__global__ __launch_bounds__(256, 2)
void gemm_nn_scaled(const float* __restrict__ W)
{
    __shared__ float As[16][128];
    __shared__ float Ws[16][128];
    const int tid = threadIdx.x;
    const int tx  = tid & 15;
    const int ty  = tid >> 4;
    const int row0 = blockIdx.y * 128;
    const int col0 = blockIdx.x * 128;
    const float* __restrict__ A = g_qcb;

    float acc[8][8];
    #pragma unroll
    for (int i = 0; i < 8; i++)
        #pragma unroll
        for (int j = 0; j < 8; j++) acc[i][j] = 0.0f;

    for (int k0 = 0; k0 < DIM; k0 += 16) {
        #pragma unroll
        for (int v = tid; v < 512; v += 256) {
            int r  = v >> 2;
            int kc = (v & 3) << 2;
            float4 a = *(const float4*)(A + (size_t)(row0 + r) * DIM + k0 + kc);
            As[kc + 0][r] = a.x; As[kc + 1][r] = a.y;
            As[kc + 2][r] = a.z; As[kc + 3][r] = a.w;
        }
        #pragma unroll
        for (int v = tid; v < 512; v += 256) {
            int kk = v >> 5;
            int nc = (v & 31) * 4;
            float4 w = *(const float4*)(W + (size_t)(k0 + kk) * DIM + col0 + nc);
            *(float4*)&Ws[kk][nc] = w;
        }
        __syncthreads();
        #pragma unroll
        for (int kk = 0; kk < 16; kk++) {
            float a[8], b[8];
            *(float4*)(a)     = *(const float4*)&As[kk][ty * 8];
            *(float4*)(a + 4) = *(const float4*)&As[kk][ty * 8 + 4];
            *(float4*)(b)     = *(const float4*)&Ws[kk][tx * 8];
            *(float4*)(b + 4) = *(const float4*)&Ws[kk][tx * 8 + 4];
            #pragma unroll
            for (int i = 0; i < 8; i++)
                #pragma unroll
                for (int j = 0; j < 8; j++)
                    acc[i][j] = fmaf(a[i], b[j], acc[i][j]);
        }
        __syncthreads();
    }

    #pragma unroll
    for (int i = 0; i < 8; i++) {
        size_t row = (size_t)(row0 + ty * 8 + i);
        float s = g_rs[row];
        float o[8];
        #pragma unroll
        for (int j = 0; j < 8; j++) o[j] = acc[i][j] * s;
        float* up = g_u + row * DIM + col0 + tx * 8;
        *(float4*)(up)     = make_float4(o[0], o[1], o[2], o[3]);
        *(float4*)(up + 4) = make_float4(o[4], o[5], o[6], o[7]);
        __nv_bfloat162* bp = (__nv_bfloat162*)(g_ub + row * DIM + col0 + tx * 8);
        bp[0] = __floats2bfloat162_rn(o[0], o[1]);
        bp[1] = __floats2bfloat162_rn(o[2], o[3]);
        bp[2] = __floats2bfloat162_rn(o[4], o[5]);
        bp[3] = __floats2bfloat162_rn(o[6], o[7]);
    }
}

// ============================================================
// K4: z -> bf16
// ============================================================
__global__ void convert_z(const float* __restrict__ z)
{
    long long n4 = QN / 4;
    long long stride = (long long)gridDim.x * blockDim.x;
    for (long long i = (long long)blockIdx.x * blockDim.x + threadIdx.x; i < n4; i += stride) {
        float4 v = ((const float4*)z)[i];
        __nv_bfloat162 p0 = __floats2bfloat162_rn(v.x, v.y);
        __nv_bfloat162 p1 = __floats2bfloat162_rn(v.z, v.w);
        uint2 o;
        o.x = *(uint32_t*)&p0;
        o.y = *(uint32_t*)&p1;
        ((uint2*)g_zb)[i] = o;
    }
}

// ============================================================
// K5: coarse bf16 HMMA pass + margin candidate collection.
// CTA: 128 z-rows x all 8192 codes (64 tiles of 128).
// smem: A band 128x512 bf16 (128KB, loaded once) + B double-buf 2x16KB + cnt.
// 8 warps, warp tile m16 x n128: per-row lanes all in one warp.
// ============================================================
#define SMA_OFF 0
#define SMB0_OFF 131072
#define SMB1_OFF 147456
#define SCNT_OFF 163840
#define COARSE_SMEM 164352

__global__ __launch_bounds__(256)
void coarse_kernel()
{
    extern __shared__ char sm[];
    const uint32_t smA  = smem_u32(sm) + SMA_OFF;
    const uint32_t smB0 = smem_u32(sm) + SMB0_OFF;
    const uint32_t smB1 = smem_u32(sm) + SMB1_OFF;
    int* scnt = (int*)(sm + SCNT_OFF);

    const int tid  = threadIdx.x;
    const int lane = tid & 31;
    const int wid  = tid >> 5;
    const int row0 = blockIdx.x * 128;
    const int warp_m0 = wid << 4;
    const int l8   = lane & 7;
    const int quad = lane >> 3;
    const int lrowA = warp_m0 + (lane >> 2);
    const int lrowB = lrowA + 8;

    if (tid < 128) scnt[tid] = 0;

    // ---- A band: 128 rows x 512 bf16 (1KB/row), swizzled, via cp.async ----
    {
        #pragma unroll
        for (int it = 0; it < 32; it++) {
            int idx = tid + (it << 8);
            int r = idx >> 6, c = idx & 63;
            const void* src = g_zb + ((size_t)(row0 + r) << 9) + (c << 3);
            uint32_t byte = ((uint32_t)r << 10) + ((uint32_t)c << 4);
            cp16(smA + (byte ^ ((r & 7) << 4)), src);
        }
    }
    // ---- prefetch B stage g=0 ----
    {
        #pragma unroll
        for (int it = 0; it < 4; it++) {
            int idx = tid + (it << 8);
            int r = idx >> 3, c = idx & 7;
            const void* src = g_ub + ((size_t)r << 9) + (c << 3);
            uint32_t byte = ((uint32_t)r << 7) + ((uint32_t)c << 4);
            cp16(smB0 + (byte ^ ((r & 7) << 4)), src);
        }
    }
    CP_COMMIT();

    float bestA = -3.4e38f, bestB = -3.4e38f;

    for (int t = 0; t < 64; t++) {
        float acc[16][4];
        #pragma unroll
        for (int i = 0; i < 16; i++)
            #pragma unroll
            for (int j = 0; j < 4; j++) acc[i][j] = 0.0f;

        for (int s = 0; s < 8; s++) {
            const int g = t * 8 + s;
            if (g + 1 < 512) {
                const int nt = (g + 1) >> 3, ns = (g + 1) & 7;
                const int n0n = nt << 7, k0n = ns << 6;
                const uint32_t dstb = ((g + 1) & 1) ? smB1 : smB0;
                #pragma unroll
                for (int it = 0; it < 4; it++) {
                    int idx = tid + (it << 8);
                    int r = idx >> 3, c = idx & 7;
                    const void* src = g_ub + ((size_t)(n0n + r) << 9) + k0n + (c << 3);
                    uint32_t byte = ((uint32_t)r << 7) + ((uint32_t)c << 4);
                    cp16(dstb + (byte ^ ((r & 7) << 4)), src);
                }
                CP_COMMIT();
                CP_WAIT(1);
            } else {
                CP_COMMIT();
                CP_WAIT(0);
            }
            __syncthreads();

            const uint32_t smB = (g & 1) ? smB1 : smB0;
            #pragma unroll
            for (int s16 = 0; s16 < 4; s16++) {
                uint32_t a[4];
                {
                    int m_r = warp_m0 + l8 + ((quad & 1) << 3);
                    int bc  = s * 128 + s16 * 32 + ((quad >> 1) << 4);
                    uint32_t ad = smA + ((((uint32_t)m_r << 10) + bc) ^ ((m_r & 7) << 4));
                    ldmatrix_x4(a, ad);
                }
                #pragma unroll
                for (int ni = 0; ni < 8; ni++) {
                    uint32_t b[4];
                    int n_r = (ni << 4) + l8 + ((quad & 1) << 3);
                    int bc  = s16 * 32 + ((quad >> 1) << 4);
                    uint32_t bd = smB + ((((uint32_t)n_r << 7) + bc) ^ ((n_r & 7) << 4));
                    ldmatrix_x4(b, bd);
                    mma_bf16(acc[2 * ni],     a, b[0], b[2]);
                    mma_bf16(acc[2 * ni + 1], a, b[1], b[3]);
                }
            }
            __syncthreads();
        }

        // ---- epilogue: add beta, running argmax + margin candidates ----
        const int n0 = t << 7;
        float tA = -3.4e38f, tB = -3.4e38f;
        #pragma unroll
        for (int ni = 0; ni < 16; ni++) {
            float2 be = *(const float2*)(g_beta + n0 + (ni << 3) + ((lane & 3) << 1));
            acc[ni][0] += be.x; acc[ni][1] += be.y;
            acc[ni][2] += be.x; acc[ni][3] += be.y;
            tA = fmaxf(tA, fmaxf(acc[ni][0], acc[ni][1]));
            tB = fmaxf(tB, fmaxf(acc[ni][2], acc[ni][3]));
        }
        tA = fmaxf(tA, __shfl_xor_sync(0xFFFFFFFFu, tA, 1));
        tA = fmaxf(tA, __shfl_xor_sync(0xFFFFFFFFu, tA, 2));
        tB = fmaxf(tB, __shfl_xor_sync(0xFFFFFFFFu, tB, 1));
        tB = fmaxf(tB, __shfl_xor_sync(0xFFFFFFFFu, tB, 2));
        bestA = fmaxf(bestA, tA);
        bestB = fmaxf(bestB, tB);
        const float thA = bestA - MARGIN, thB = bestB - MARGIN;

        #pragma unroll
        for (int ni = 0; ni < 16; ni++) {
            int nb = n0 + (ni << 3) + ((lane & 3) << 1);
            if (acc[ni][0] > thA) {
                int sl = atomicAdd(&scnt[lrowA], 1);
                if (sl < CAP) g_cand[((size_t)(row0 + lrowA) << 5) + sl] = (unsigned)nb;
            }
            if (acc[ni][1] > thA) {
                int sl = atomicAdd(&scnt[lrowA], 1);
                if (sl < CAP) g_cand[((size_t)(row0 + lrowA) << 5) + sl] = (unsigned)(nb + 1);
            }
            if (acc[ni][2] > thB) {
                int sl = atomicAdd(&scnt[lrowB], 1);
                if (sl < CAP) g_cand[((size_t)(row0 + lrowB) << 5) + sl] = (unsigned)nb;
            }
            if (acc[ni][3] > thB) {
                int sl = atomicAdd(&scnt[lrowB], 1);
                if (sl < CAP) g_cand[((size_t)(row0 + lrowB) << 5) + sl] = (unsigned)(nb + 1);
            }
        }
    }

    __syncthreads();
    if (tid < 128) g_ccnt[row0 + tid] = scnt[tid];
}

// ============================================================
// K6: exact fp32 rescore: s = z . u_n + beta_n.  One warp per z-row.
// ============================================================
__global__ __launch_bounds__(256)
void rescore(const float* __restrict__ z)
{
    const int row  = blockIdx.x * 8 + (threadIdx.x >> 5);
    const int lane = threadIdx.x & 31;
    const float* zp = z + (size_t)row * DIM;
    float4 zr[4];
    #pragma unroll
    for (int it = 0; it < 4; it++)
        zr[it] = *(const float4*)(zp + lane * 16 + it * 4);

    int cnt = g_ccnt[row];
    float bv = -3.4e38f;
    int   bi = 0x7FFFFFFF;

    if (cnt <= CAP) {
        for (int c = 0; c < cnt; c++) {
            int idx = (int)g_cand[((size_t)row << 5) + c];
            const float* ur = g_u + (size_t)idx * DIM;
            float s = 0.0f;
            #pragma unroll
            for (int it = 0; it < 4; it++) {
                float4 uv = *(const float4*)(ur + lane * 16 + it * 4);
                s = fmaf(zr[it].x, uv.x, s);
                s = fmaf(zr[it].y, uv.y, s);
                s = fmaf(zr[it].z, uv.z, s);
                s = fmaf(zr[it].w, uv.w, s);
            }
            #pragma unroll
            for (int o = 16; o > 0; o >>= 1) s += __shfl_xor_sync(0xFFFFFFFFu, s, o);
            s += g_beta[idx];
            if (s > bv || (s == bv && idx < bi)) { bv = s; bi = idx; }
        }
    } else {
        // overflow fallback: exact scan of all codes (ascending n, first max kept)
        for (int n = 0; n < N_CB; n++) {
            const float* ur = g_u + (size_t)n * DIM;
            float s = 0.0f;
            #pragma unroll
            for (int it = 0; it < 4; it++) {
                float4 uv = *(const float4*)(ur + lane * 16 + it * 4);
                s = fmaf(zr[it].x, uv.x, s);
                s = fmaf(zr[it].y, uv.y, s);
                s = fmaf(zr[it].z, uv.z, s);
                s = fmaf(zr[it].w, uv.w, s);
            }
            #pragma unroll
            for (int o = 16; o > 0; o >>= 1) s += __shfl_xor_sync(0xFFFFFFFFu, s, o);
            s += g_beta[n];
            if (s > bv) { bv = s; bi = n; }
        }
    }
    if (lane == 0) g_idx[row] = bi;
}

// ============================================================
// K7: quantized = z + (q - z), per-row (q-z)^2 partial, idx tail
// ============================================================
__global__ void gather_loss(const float* __restrict__ z, float* __restrict__ out,
                            long long out_size)
{
    int row = blockIdx.x;
    int t   = threadIdx.x;   // 128 threads
    int id  = g_idx[row];
    const float* q  = g_qcb + (size_t)id * DIM;
    const float* zr = z + (size_t)row * DIM;
    float* oq = out + (size_t)row * DIM;

    float s = 0.0f;
    #pragma unroll
    for (int c = t * 4; c < DIM; c += 512) {
        float4 qv = *(const float4*)(q + c);
        float4 zv = *(const float4*)(zr + c);
        float4 o;
        float d;
        d = qv.x - zv.x; o.x = zv.x + d; s = fmaf(d, d, s);
        d = qv.y - zv.y; o.y = zv.y + d; s = fmaf(d, d, s);
        d = qv.z - zv.z; o.z = zv.z + d; s = fmaf(d, d, s);
        d = qv.w - zv.w; o.w = zv.w + d; s = fmaf(d, d, s);
        *(float4*)(oq + c) = o;
    }

    __shared__ float red[128];
    red[t] = s;
    __syncthreads();
    #pragma unroll
    for (int off = 64; off > 0; off >>= 1) {
        if (t < off) red[t] += red[t + off];
        __syncthreads();
    }
    if (t == 0) {
        g_partial[row] = red[0];
        long long pos = (long long)QN + 1 + row;
        if (pos < out_size) out[pos] = (float)id;
    }
}

__global__ void finalize_loss(float* __restrict__ out, long long out_size)
{
    __shared__ float red[256];
    int t = threadIdx.x;
    float s = 0.0f;
    for (int i = t; i < M_Z; i += 256) s += g_partial[i];
    red[t] = s;
    __syncthreads();
    #pragma unroll
    for (int off = 128; off > 0; off >>= 1) {
        if (t < off) red[t] += red[t + off];
        __syncthreads();
    }
    if (t == 0 && (long long)QN < out_size)
        out[QN] = red[0] * (1.25f / 16777216.0f);
}

__global__ void zero_range(float* __restrict__ out, long long begin, long long end)
{
    long long stride = (long long)gridDim.x * blockDim.x;
    for (long long i = begin + (long long)blockIdx.x * blockDim.x + threadIdx.x;
         i < end; i += stride)
        out[i] = 0.0f;
}

// ============================================================
extern "C" void kernel_launch(void* const* d_in, const int* in_sizes, int n_in,
                              void* d_out, int out_size)
{
    const float* z     = (const float*)d_in[0];   // [8,4096,512]
    const float* emb   = (const float*)d_in[1];   // [8192,512]
    const float* emb_w = (const float*)d_in[2];   // [512,512]
    const float* emb_b = (const float*)d_in[3];   // [512]
    const float* zw    = (const float*)d_in[4];   // [512,512]
    const float* zb    = (const float*)d_in[5];   // [512]
    // d_in[6] = l2_scale: positive per-row scaling, argmin-invariant -> unused
    float* out = (float*)d_out;
    long long osz = (long long)out_size;

    cudaFuncSetAttribute(coarse_kernel,
                         cudaFuncAttributeMaxDynamicSharedMemorySize, COARSE_SMEM);

    // K1: quant_codebook = emb @ emb_w^T + emb_b
    gemm_bias_nt<<<dim3(4, 64), 256>>>(emb, emb_w, emb_b, DIM);
    // K2: row norms + beta = (z_proj_b . c)/||c||
    rownorm_beta<<<N_CB / 8, 256>>>(zb);
    // K3: U = diag(1/||c||)(qcb @ zw)   (g_qcb referenced device-side)
    gemm_nn_scaled<<<dim3(4, 64), 256>>>(zw);
    // K4: z -> bf16
    convert_z<<<2048, 256>>>(z);
    // K5: bf16 HMMA coarse pass -> candidates
    coarse_kernel<<<M_Z / 128, 256, COARSE_SMEM>>>();
    // K6: exact fp32 rescore -> g_idx
    rescore<<<M_Z / 8, 256>>>(z);
    // K7: outputs
    gather_loss<<<M_Z, 128>>>(z, out, osz);
    finalize_loss<<<1, 256>>>(out, osz);
    long long need = (long long)QN + 1 + M_Z;
    if (osz > need) zero_range<<<256, 256>>>(out, need, osz);
}